// round 6
// baseline (speedup 1.0000x reference)
#include <cuda_runtime.h>
#include <math.h>

#define D      512
#define B      256
#define FOURD  2048
#define QS     1024   // 2*D
#define SPLITS 16
#define NW     4      // warps per attn block (128 threads)

#define BM 128
#define BN 128
#define BK 16
#define KSPLIT 8
#define KCH (QS / KSPLIT)   // 128

// ---- scratch (no allocations allowed) ----
__device__ float g_Wcomb[FOURD * QS];   // [2048,1024] K-major
__device__ float g_bsum[FOURD];
__device__ float g_qstar[B * QS];       // [h | r]
__device__ float g_c[B * D];
__device__ float g_gpart[KSPLIT][B * FOURD];
__device__ int   g_segoff[B + 1];
// split-attention partials + completion counters
__device__ float g_pm[B * SPLITS];
__device__ float g_pd[B * SPLITS];
__device__ float g_pr[B * SPLITS * D];
__device__ int   g_cnt[B];              // zero-init; reset by combine -> replay-safe

__device__ __forceinline__ float sigf(float v) { return 1.0f / (1.0f + expf(-v)); }

// ---------------- fused init: wcomb + step0 + segscan in one launch ----------------
#define WCOMB_BLKS (FOURD * QS / 4 / 256)   // 2048
#define STEP0_BLKS (B * D / 256)            // 512
__global__ void k_init(const void* __restrict__ raw, int N,
                       const float* __restrict__ W_ih, const float* __restrict__ W_hh,
                       const float* __restrict__ b_ih, const float* __restrict__ b_hh) {
    int blk = blockIdx.x;
    int t = threadIdx.x;
    if (blk < WCOMB_BLKS) {
        // W_comb = [W_ih[:, :D] + W_hh | W_ih[:, D:]], bsum = b_ih + b_hh
        int i4 = blk * 256 + t;
        float4 v = ((const float4*)W_ih)[i4];
        int idx = i4 * 4;
        int k = idx & (QS - 1);
        int n = idx >> 10;
        if (k < D) {
            float4 w = *(const float4*)(W_hh + n * D + k);
            v.x += w.x; v.y += w.y; v.z += w.z; v.w += w.w;
        }
        ((float4*)g_Wcomb)[i4] = v;
        if (i4 < FOURD) g_bsum[i4] = b_ih[i4] + b_hh[i4];
    } else if (blk < WCOMB_BLKS + STEP0_BLKS) {
        // step 0: h,c from biases only (q_star = 0)
        int idx = (blk - WCOMB_BLKS) * 256 + t;
        int j = idx & (D - 1);
        float gi = b_ih[j]         + b_hh[j];
        float gg = b_ih[2 * D + j] + b_hh[2 * D + j];
        float go = b_ih[3 * D + j] + b_hh[3 * D + j];
        float c  = sigf(gi) * tanhf(gg);
        float h  = sigf(go) * tanhf(c);
        int b = idx >> 9;
        g_c[idx] = c;
        g_qstar[b * QS + j] = h;
    } else {
        // segment-boundary scan; auto-detect int32 vs int64 batch
        const int* p32 = (const int*)raw;
        bool is64 = (p32[N - 1] == 0) || (p32[N - 2] == 0);
        int i = (blk - WCOMB_BLKS - STEP0_BLKS) * 256 + t;
        if (i >= N) return;
        int cur = is64 ? (int)((const long long*)raw)[i] : p32[i];
        if (i == 0) {
            for (int j = 0; j <= cur; j++) g_segoff[j] = 0;
        } else {
            int prev = is64 ? (int)((const long long*)raw)[i - 1] : p32[i - 1];
            for (int j = prev + 1; j <= cur; j++) g_segoff[j] = i;
        }
        if (i == N - 1) {
            for (int j = cur + 1; j <= B; j++) g_segoff[j] = N;
        }
    }
}

// ---------------- LSTM elementwise for steps 1,2 (sums K-split partials + bias) ----------------
__global__ void k_lstm_ew() {
    int idx = blockIdx.x * blockDim.x + threadIdx.x;
    if (idx >= B * D) return;
    int b = idx >> 9, j = idx & (D - 1);
    float gi = g_bsum[j], gf = g_bsum[D + j], gg = g_bsum[2 * D + j], go = g_bsum[3 * D + j];
    #pragma unroll
    for (int z = 0; z < KSPLIT; z++) {
        const float* g = &g_gpart[z][(size_t)b * FOURD];
        gi += g[j]; gf += g[D + j]; gg += g[2 * D + j]; go += g[3 * D + j];
    }
    float c = sigf(gf) * g_c[idx] + sigf(gi) * tanhf(gg);
    float h = sigf(go) * tanhf(c);
    g_c[idx] = c;
    g_qstar[b * QS + j] = h;
}

// ---------------- gates GEMM: split-K, 128x128 tile, 8x8 microtile, f32x2 FMA,
// ----------------              register-staged double-buffered global loads ----------------
__global__ void __launch_bounds__(256) k_gemm_gates() {
    __shared__ __align__(16) float As[BK][BM + 4];
    __shared__ __align__(16) float Bs[BK][BN + 4];
    int n0 = blockIdx.x * BN, m0 = blockIdx.y * BM, kc = blockIdx.z * KCH;
    int t = threadIdx.x;
    int tx = t & 15, ty = t >> 4;
    unsigned long long acc2[8][4];
    #pragma unroll
    for (int i = 0; i < 8; i++)
        #pragma unroll
        for (int j = 0; j < 4; j++) acc2[i][j] = 0ull;

    int rowi[2], kqi[2];
    #pragma unroll
    for (int s = 0; s < 2; s++) {
        int i4 = t + s * 256;
        rowi[s] = i4 >> 2;
        kqi[s]  = (i4 & 3) * 4;
    }

    float4 va[2], vb[2];
    #pragma unroll
    for (int s = 0; s < 2; s++) {
        va[s] = *(const float4*)(g_qstar + (size_t)(m0 + rowi[s]) * QS + kc + kqi[s]);
        vb[s] = *(const float4*)(g_Wcomb + (size_t)(n0 + rowi[s]) * QS + kc + kqi[s]);
    }

    for (int k0 = 0; k0 < KCH; k0 += BK) {
        #pragma unroll
        for (int s = 0; s < 2; s++) {
            int row = rowi[s], kq = kqi[s];
            As[kq + 0][row] = va[s].x; As[kq + 1][row] = va[s].y;
            As[kq + 2][row] = va[s].z; As[kq + 3][row] = va[s].w;
            Bs[kq + 0][row] = vb[s].x; Bs[kq + 1][row] = vb[s].y;
            Bs[kq + 2][row] = vb[s].z; Bs[kq + 3][row] = vb[s].w;
        }
        __syncthreads();
        if (k0 + BK < KCH) {
            #pragma unroll
            for (int s = 0; s < 2; s++) {
                va[s] = *(const float4*)(g_qstar + (size_t)(m0 + rowi[s]) * QS + kc + k0 + BK + kqi[s]);
                vb[s] = *(const float4*)(g_Wcomb + (size_t)(n0 + rowi[s]) * QS + kc + k0 + BK + kqi[s]);
            }
        }
        #pragma unroll
        for (int kk = 0; kk < BK; kk++) {
            float a[8];
            *(float4*)(a)     = *(const float4*)&As[kk][ty * 8];
            *(float4*)(a + 4) = *(const float4*)&As[kk][ty * 8 + 4];
            unsigned long long b2[4];
            {
                ulonglong2 bl0 = *(const ulonglong2*)&Bs[kk][tx * 8];
                ulonglong2 bl1 = *(const ulonglong2*)&Bs[kk][tx * 8 + 4];
                b2[0] = bl0.x; b2[1] = bl0.y; b2[2] = bl1.x; b2[3] = bl1.y;
            }
            #pragma unroll
            for (int i = 0; i < 8; i++) {
                unsigned long long a2;
                asm("mov.b64 %0, {%1, %1};" : "=l"(a2) : "r"(__float_as_uint(a[i])));
                #pragma unroll
                for (int j = 0; j < 4; j++)
                    asm("fma.rn.f32x2 %0, %1, %2, %0;"
                        : "+l"(acc2[i][j]) : "l"(a2), "l"(b2[j]));
            }
        }
        __syncthreads();
    }
    #pragma unroll
    for (int i = 0; i < 8; i++) {
        int mrow = m0 + ty * 8 + i;
        unsigned long long* dst =
            (unsigned long long*)&g_gpart[blockIdx.z][(size_t)mrow * FOURD + n0 + tx * 8];
        *(ulonglong2*)(dst)     = make_ulonglong2(acc2[i][0], acc2[i][1]);
        *(ulonglong2*)(dst + 2) = make_ulonglong2(acc2[i][2], acc2[i][3]);
    }
}

// ---------------- split segment attention + fused last-block combine ----------------
// lane l owns cols {c*128 + l*4 .. +3}; 3-buffer rotation keeps 2 nodes in flight per warp.
__global__ void __launch_bounds__(128) k_attn_part(const float* __restrict__ x) {
    __shared__ __align__(16) float q_sh[D];
    __shared__ __align__(16) float rsh[NW][D];
    __shared__ float msh[NW], dsh[NW];
    __shared__ int is_last;

    int b  = blockIdx.x / SPLITS;
    int sp = blockIdx.x % SPLITS;
    int t = threadIdx.x;
    int w = t >> 5, lane = t & 31;

    int segs = g_segoff[b], sege = g_segoff[b + 1];
    int total = sege - segs;
    int start = segs + (int)(((long long)total * sp) / SPLITS);
    int end   = segs + (int)(((long long)total * (sp + 1)) / SPLITS);

    #pragma unroll
    for (int i = 0; i < 4; i++) q_sh[t + i * 128] = g_qstar[b * QS + t + i * 128];
    __syncthreads();

    float qr[16];
    #pragma unroll
    for (int c = 0; c < 4; c++) {
        float4 qv = *(const float4*)&q_sh[c * 128 + lane * 4];
        qr[c * 4 + 0] = qv.x; qr[c * 4 + 1] = qv.y;
        qr[c * 4 + 2] = qv.z; qr[c * 4 + 3] = qv.w;
    }

    float m = -INFINITY, d = 0.0f;
    float r[16];
    #pragma unroll
    for (int j = 0; j < 16; j++) r[j] = 0.0f;

    int n = start + w;
    float4 A0, A1, A2, A3, B0, B1, B2, B3;
    if (n < end) {
        const float* p = x + (size_t)n * D;
        A0 = ((const float4*)(p      ))[lane];
        A1 = ((const float4*)(p + 128))[lane];
        A2 = ((const float4*)(p + 256))[lane];
        A3 = ((const float4*)(p + 384))[lane];
    }
    if (n + NW < end) {
        const float* p = x + (size_t)(n + NW) * D;
        B0 = ((const float4*)(p      ))[lane];
        B1 = ((const float4*)(p + 128))[lane];
        B2 = ((const float4*)(p + 256))[lane];
        B3 = ((const float4*)(p + 384))[lane];
    }
    while (n < end) {
        float4 C0, C1, C2, C3;
        bool haveC = (n + 2 * NW < end);
        if (haveC) {
            const float* p = x + (size_t)(n + 2 * NW) * D;
            C0 = ((const float4*)(p      ))[lane];
            C1 = ((const float4*)(p + 128))[lane];
            C2 = ((const float4*)(p + 256))[lane];
            C3 = ((const float4*)(p + 384))[lane];
        }
        float s = A0.x * qr[0]  + A0.y * qr[1]  + A0.z * qr[2]  + A0.w * qr[3]
                + A1.x * qr[4]  + A1.y * qr[5]  + A1.z * qr[6]  + A1.w * qr[7]
                + A2.x * qr[8]  + A2.y * qr[9]  + A2.z * qr[10] + A2.w * qr[11]
                + A3.x * qr[12] + A3.y * qr[13] + A3.z * qr[14] + A3.w * qr[15];
        #pragma unroll
        for (int o = 16; o > 0; o >>= 1) s += __shfl_xor_sync(0xffffffffu, s, o);

        if (s > m) {
            float al = __expf(m - s);   // first iteration: exp(-inf) = 0
            d = d * al + 1.0f;
            r[0]  = r[0]  * al + A0.x;  r[1]  = r[1]  * al + A0.y;
            r[2]  = r[2]  * al + A0.z;  r[3]  = r[3]  * al + A0.w;
            r[4]  = r[4]  * al + A1.x;  r[5]  = r[5]  * al + A1.y;
            r[6]  = r[6]  * al + A1.z;  r[7]  = r[7]  * al + A1.w;
            r[8]  = r[8]  * al + A2.x;  r[9]  = r[9]  * al + A2.y;
            r[10] = r[10] * al + A2.z;  r[11] = r[11] * al + A2.w;
            r[12] = r[12] * al + A3.x;  r[13] = r[13] * al + A3.y;
            r[14] = r[14] * al + A3.z;  r[15] = r[15] * al + A3.w;
            m = s;
        } else {
            float wv = __expf(s - m);
            d += wv;
            r[0]  += wv * A0.x;  r[1]  += wv * A0.y;  r[2]  += wv * A0.z;  r[3]  += wv * A0.w;
            r[4]  += wv * A1.x;  r[5]  += wv * A1.y;  r[6]  += wv * A1.z;  r[7]  += wv * A1.w;
            r[8]  += wv * A2.x;  r[9]  += wv * A2.y;  r[10] += wv * A2.z;  r[11] += wv * A2.w;
            r[12] += wv * A3.x;  r[13] += wv * A3.y;  r[14] += wv * A3.z;  r[15] += wv * A3.w;
        }
        // rotate buffers
        A0 = B0; A1 = B1; A2 = B2; A3 = B3;
        B0 = C0; B1 = C1; B2 = C2; B3 = C3;
        n += NW;
    }

    // per-warp partials to shared (canonical column order)
    if (lane == 0) { msh[w] = m; dsh[w] = d; }
    #pragma unroll
    for (int c = 0; c < 4; c++)
        *(float4*)&rsh[w][c * 128 + lane * 4] =
            make_float4(r[c * 4], r[c * 4 + 1], r[c * 4 + 2], r[c * 4 + 3]);
    __syncthreads();

    // block combine: thread t owns cols t, t+128, t+256, t+384
    float M = msh[0];
    #pragma unroll
    for (int p = 1; p < NW; p++) M = fmaxf(M, msh[p]);
    float Mg = isfinite(M) ? M : 0.0f;
    float dd = 0.0f, rr[4] = {0.0f, 0.0f, 0.0f, 0.0f};
    #pragma unroll
    for (int p = 0; p < NW; p++) {
        float sc = __expf(msh[p] - Mg);
        dd += dsh[p] * sc;
        #pragma unroll
        for (int i = 0; i < 4; i++) rr[i] += rsh[p][t + i * 128] * sc;
    }
    int pid = b * SPLITS + sp;
    #pragma unroll
    for (int i = 0; i < 4; i++) g_pr[(size_t)pid * D + t + i * 128] = rr[i];
    if (t == 0) { g_pm[pid] = M; g_pd[pid] = dd; }

    // last block for this graph merges all split partials
    __threadfence();
    if (t == 0) {
        int c = atomicAdd(&g_cnt[b], 1);
        is_last = (c == SPLITS - 1);
    }
    __syncthreads();
    if (!is_last) return;

    __shared__ float sm[SPLITS], sd[SPLITS];
    if (t < SPLITS) {
        sm[t] = g_pm[b * SPLITS + t];
        sd[t] = g_pd[b * SPLITS + t];
    }
    __syncthreads();
    float MM = -INFINITY;
    #pragma unroll
    for (int p = 0; p < SPLITS; p++) MM = fmaxf(MM, sm[p]);
    if (!isfinite(MM)) MM = 0.0f;
    float denom = 0.0f;
    float scale[SPLITS];
    #pragma unroll
    for (int p = 0; p < SPLITS; p++) {
        scale[p] = expf(sm[p] - MM);
        denom += sd[p] * scale[p];
    }
    float inv = 1.0f / (denom + 1e-16f);
    float fr[4] = {0.0f, 0.0f, 0.0f, 0.0f};
    #pragma unroll
    for (int p = 0; p < SPLITS; p++) {
        const float* pr = g_pr + (size_t)(b * SPLITS + p) * D;
        #pragma unroll
        for (int i = 0; i < 4; i++) fr[i] += pr[t + i * 128] * scale[p];
    }
    #pragma unroll
    for (int i = 0; i < 4; i++) g_qstar[b * QS + D + t + i * 128] = fr[i] * inv;
    if (t == 0) g_cnt[b] = 0;   // reset for next pass / next replay
}

// ---------------- projection: out[b,o] = qstar[b,:] . W_proj[o,:] + b_proj[o] ----------------
__global__ void k_proj(const float* __restrict__ Wp, const float* __restrict__ bp,
                       float* __restrict__ out) {
    int gw = (blockIdx.x * 256 + threadIdx.x) >> 5;
    int lane = threadIdx.x & 31;
    int bb = gw >> 8, o = gw & 255;
    const float* qr = g_qstar + bb * QS;
    const float* wr = Wp + o * QS;
    float s = 0.0f;
    #pragma unroll
    for (int it = 0; it < QS / 128; it++) {
        int k = lane * 4 + it * 128;
        float4 a = *(const float4*)(qr + k);
        float4 w = *(const float4*)(wr + k);
        s += a.x * w.x + a.y * w.y + a.z * w.z + a.w * w.w;
    }
    #pragma unroll
    for (int off = 16; off > 0; off >>= 1) s += __shfl_xor_sync(0xffffffffu, s, off);
    if (lane == 0) out[gw] = s + bp[o];
}

// ---------------- launch ----------------
extern "C" void kernel_launch(void* const* d_in, const int* in_sizes, int n_in,
                              void* d_out, int out_size) {
    const float* x      = (const float*)d_in[0];
    const void*  batch  = d_in[1];
    const float* W_ih   = (const float*)d_in[2];
    const float* W_hh   = (const float*)d_in[3];
    const float* b_ih   = (const float*)d_in[4];
    const float* b_hh   = (const float*)d_in[5];
    const float* W_proj = (const float*)d_in[6];
    const float* b_proj = (const float*)d_in[7];
    (void)n_in; (void)out_size;
    int N = in_sizes[1];

    int init_blocks = WCOMB_BLKS + STEP0_BLKS + (N + 255) / 256;
    k_init<<<init_blocks, 256>>>(batch, N, W_ih, W_hh, b_ih, b_hh);

    // step 0 attention (h from biases written by k_init)
    k_attn_part<<<B * SPLITS, 128>>>(x);

    // steps 1,2
    for (int s = 1; s < 3; s++) {
        k_gemm_gates<<<dim3(FOURD / BN, B / BM, KSPLIT), 256>>>();
        k_lstm_ew<<<(B * D + 255) / 256, 256>>>();
        k_attn_part<<<B * SPLITS, 128>>>(x);
    }

    k_proj<<<(B * 256) / 8, 256>>>(W_proj, b_proj, (float*)d_out);
}

// round 7
// speedup vs baseline: 1.0156x; 1.0156x over previous
#include <cuda_runtime.h>
#include <math.h>

#define D      512
#define B      256
#define FOURD  2048
#define QS     1024   // 2*D
#define SPLITS 8
#define NW     8      // warps per attn block (256 threads)

#define BM 128
#define BN 128
#define BK 16
#define KSPLIT 8
#define KCH (QS / KSPLIT)   // 128

// ---- scratch (no allocations allowed) ----
__device__ float g_Wcomb[FOURD * QS];   // [2048,1024] K-major
__device__ float g_bsum[FOURD];
__device__ float g_qstar[B * QS];       // [h | r]
__device__ float g_c[B * D];
__device__ float g_gpart[KSPLIT][B * FOURD];
__device__ int   g_segoff[B + 1];
// split-attention partials + completion counters
__device__ float g_pm[B * SPLITS];
__device__ float g_pd[B * SPLITS];
__device__ float g_pr[B * SPLITS * D];
__device__ int   g_cnt[B];              // zero-init; reset by combine -> replay-safe

__device__ __forceinline__ float sigf(float v) { return 1.0f / (1.0f + expf(-v)); }

// ---------------- fused init: wcomb + step0 + segscan in one launch ----------------
#define WCOMB_BLKS (FOURD * QS / 4 / 256)   // 2048
#define STEP0_BLKS (B * D / 256)            // 512
__global__ void k_init(const void* __restrict__ raw, int N,
                       const float* __restrict__ W_ih, const float* __restrict__ W_hh,
                       const float* __restrict__ b_ih, const float* __restrict__ b_hh) {
    int blk = blockIdx.x;
    int t = threadIdx.x;
    if (blk < WCOMB_BLKS) {
        // W_comb = [W_ih[:, :D] + W_hh | W_ih[:, D:]], bsum = b_ih + b_hh
        int i4 = blk * 256 + t;
        float4 v = ((const float4*)W_ih)[i4];
        int idx = i4 * 4;
        int k = idx & (QS - 1);
        int n = idx >> 10;
        if (k < D) {
            float4 w = *(const float4*)(W_hh + n * D + k);
            v.x += w.x; v.y += w.y; v.z += w.z; v.w += w.w;
        }
        ((float4*)g_Wcomb)[i4] = v;
        if (i4 < FOURD) g_bsum[i4] = b_ih[i4] + b_hh[i4];
    } else if (blk < WCOMB_BLKS + STEP0_BLKS) {
        // step 0: h,c from biases only (q_star = 0)
        int idx = (blk - WCOMB_BLKS) * 256 + t;
        int j = idx & (D - 1);
        float gi = b_ih[j]         + b_hh[j];
        float gg = b_ih[2 * D + j] + b_hh[2 * D + j];
        float go = b_ih[3 * D + j] + b_hh[3 * D + j];
        float c  = sigf(gi) * tanhf(gg);
        float h  = sigf(go) * tanhf(c);
        int b = idx >> 9;
        g_c[idx] = c;
        g_qstar[b * QS + j] = h;
    } else {
        // segment-boundary scan; auto-detect int32 vs int64 batch
        const int* p32 = (const int*)raw;
        bool is64 = (p32[N - 1] == 0) || (p32[N - 2] == 0);
        int i = (blk - WCOMB_BLKS - STEP0_BLKS) * 256 + t;
        if (i >= N) return;
        int cur = is64 ? (int)((const long long*)raw)[i] : p32[i];
        if (i == 0) {
            for (int j = 0; j <= cur; j++) g_segoff[j] = 0;
        } else {
            int prev = is64 ? (int)((const long long*)raw)[i - 1] : p32[i - 1];
            for (int j = prev + 1; j <= cur; j++) g_segoff[j] = i;
        }
        if (i == N - 1) {
            for (int j = cur + 1; j <= B; j++) g_segoff[j] = N;
        }
    }
}

// ---------------- LSTM elementwise, float4-vectorized (sums K-split partials + bias) ----------------
__global__ void k_lstm_ew() {
    int idx = blockIdx.x * blockDim.x + threadIdx.x;   // over B*D/4
    if (idx >= B * D / 4) return;
    int b = idx >> 7;
    int j = (idx & 127) * 4;
    float4 gi = *(const float4*)&g_bsum[j];
    float4 gf = *(const float4*)&g_bsum[D + j];
    float4 gg = *(const float4*)&g_bsum[2 * D + j];
    float4 go = *(const float4*)&g_bsum[3 * D + j];
    #pragma unroll
    for (int z = 0; z < KSPLIT; z++) {
        const float* g = &g_gpart[z][(size_t)b * FOURD];
        float4 a = *(const float4*)&g[j];
        float4 f = *(const float4*)&g[D + j];
        float4 c = *(const float4*)&g[2 * D + j];
        float4 o = *(const float4*)&g[3 * D + j];
        gi.x += a.x; gi.y += a.y; gi.z += a.z; gi.w += a.w;
        gf.x += f.x; gf.y += f.y; gf.z += f.z; gf.w += f.w;
        gg.x += c.x; gg.y += c.y; gg.z += c.z; gg.w += c.w;
        go.x += o.x; go.y += o.y; go.z += o.z; go.w += o.w;
    }
    float4 cold = *(const float4*)&g_c[b * D + j];
    float4 cnew, hnew;
    cnew.x = sigf(gf.x) * cold.x + sigf(gi.x) * tanhf(gg.x);
    cnew.y = sigf(gf.y) * cold.y + sigf(gi.y) * tanhf(gg.y);
    cnew.z = sigf(gf.z) * cold.z + sigf(gi.z) * tanhf(gg.z);
    cnew.w = sigf(gf.w) * cold.w + sigf(gi.w) * tanhf(gg.w);
    hnew.x = sigf(go.x) * tanhf(cnew.x);
    hnew.y = sigf(go.y) * tanhf(cnew.y);
    hnew.z = sigf(go.z) * tanhf(cnew.z);
    hnew.w = sigf(go.w) * tanhf(cnew.w);
    *(float4*)&g_c[b * D + j] = cnew;
    *(float4*)&g_qstar[b * QS + j] = hnew;
}

// ---------------- gates GEMM: split-K, 128x128 tile, 8x8 microtile, f32x2 FMA,
// ----------------              register-staged double-buffered global loads ----------------
__global__ void __launch_bounds__(256) k_gemm_gates() {
    __shared__ __align__(16) float As[BK][BM + 4];
    __shared__ __align__(16) float Bs[BK][BN + 4];
    int n0 = blockIdx.x * BN, m0 = blockIdx.y * BM, kc = blockIdx.z * KCH;
    int t = threadIdx.x;
    int tx = t & 15, ty = t >> 4;
    unsigned long long acc2[8][4];
    #pragma unroll
    for (int i = 0; i < 8; i++)
        #pragma unroll
        for (int j = 0; j < 4; j++) acc2[i][j] = 0ull;

    int rowi[2], kqi[2];
    #pragma unroll
    for (int s = 0; s < 2; s++) {
        int i4 = t + s * 256;
        rowi[s] = i4 >> 2;
        kqi[s]  = (i4 & 3) * 4;
    }

    float4 va[2], vb[2];
    #pragma unroll
    for (int s = 0; s < 2; s++) {
        va[s] = *(const float4*)(g_qstar + (size_t)(m0 + rowi[s]) * QS + kc + kqi[s]);
        vb[s] = *(const float4*)(g_Wcomb + (size_t)(n0 + rowi[s]) * QS + kc + kqi[s]);
    }

    for (int k0 = 0; k0 < KCH; k0 += BK) {
        #pragma unroll
        for (int s = 0; s < 2; s++) {
            int row = rowi[s], kq = kqi[s];
            As[kq + 0][row] = va[s].x; As[kq + 1][row] = va[s].y;
            As[kq + 2][row] = va[s].z; As[kq + 3][row] = va[s].w;
            Bs[kq + 0][row] = vb[s].x; Bs[kq + 1][row] = vb[s].y;
            Bs[kq + 2][row] = vb[s].z; Bs[kq + 3][row] = vb[s].w;
        }
        __syncthreads();
        if (k0 + BK < KCH) {
            #pragma unroll
            for (int s = 0; s < 2; s++) {
                va[s] = *(const float4*)(g_qstar + (size_t)(m0 + rowi[s]) * QS + kc + k0 + BK + kqi[s]);
                vb[s] = *(const float4*)(g_Wcomb + (size_t)(n0 + rowi[s]) * QS + kc + k0 + BK + kqi[s]);
            }
        }
        #pragma unroll
        for (int kk = 0; kk < BK; kk++) {
            float a[8];
            *(float4*)(a)     = *(const float4*)&As[kk][ty * 8];
            *(float4*)(a + 4) = *(const float4*)&As[kk][ty * 8 + 4];
            unsigned long long b2[4];
            {
                ulonglong2 bl0 = *(const ulonglong2*)&Bs[kk][tx * 8];
                ulonglong2 bl1 = *(const ulonglong2*)&Bs[kk][tx * 8 + 4];
                b2[0] = bl0.x; b2[1] = bl0.y; b2[2] = bl1.x; b2[3] = bl1.y;
            }
            #pragma unroll
            for (int i = 0; i < 8; i++) {
                unsigned long long a2;
                asm("mov.b64 %0, {%1, %1};" : "=l"(a2) : "r"(__float_as_uint(a[i])));
                #pragma unroll
                for (int j = 0; j < 4; j++)
                    asm("fma.rn.f32x2 %0, %1, %2, %0;"
                        : "+l"(acc2[i][j]) : "l"(a2), "l"(b2[j]));
            }
        }
        __syncthreads();
    }
    #pragma unroll
    for (int i = 0; i < 8; i++) {
        int mrow = m0 + ty * 8 + i;
        unsigned long long* dst =
            (unsigned long long*)&g_gpart[blockIdx.z][(size_t)mrow * FOURD + n0 + tx * 8];
        *(ulonglong2*)(dst)     = make_ulonglong2(acc2[i][0], acc2[i][1]);
        *(ulonglong2*)(dst + 2) = make_ulonglong2(acc2[i][2], acc2[i][3]);
    }
}

// ---------------- split segment attention (round-5 shape) + fused last-block combine ----------------
// lane l owns cols {c*128 + l*4 .. +3}; depth-1 register prefetch, 8 warps/block, SPLITS=8.
__global__ void __launch_bounds__(256) k_attn_part(const float* __restrict__ x) {
    __shared__ __align__(16) float q_sh[D];
    __shared__ __align__(16) float rsh[NW][D];
    __shared__ float msh[NW], dsh[NW];
    __shared__ int is_last;

    int b  = blockIdx.x / SPLITS;
    int sp = blockIdx.x % SPLITS;
    int t = threadIdx.x;
    int w = t >> 5, lane = t & 31;

    int segs = g_segoff[b], sege = g_segoff[b + 1];
    int total = sege - segs;
    int start = segs + (int)(((long long)total * sp) / SPLITS);
    int end   = segs + (int)(((long long)total * (sp + 1)) / SPLITS);

    q_sh[t]       = g_qstar[b * QS + t];
    q_sh[t + 256] = g_qstar[b * QS + t + 256];
    __syncthreads();

    float qr[16];
    #pragma unroll
    for (int c = 0; c < 4; c++) {
        float4 qv = *(const float4*)&q_sh[c * 128 + lane * 4];
        qr[c * 4 + 0] = qv.x; qr[c * 4 + 1] = qv.y;
        qr[c * 4 + 2] = qv.z; qr[c * 4 + 3] = qv.w;
    }

    float m = -INFINITY, d = 0.0f;
    float r[16];
    #pragma unroll
    for (int j = 0; j < 16; j++) r[j] = 0.0f;

    int n = start + w;
    float4 xb0, xb1, xb2, xb3;
    if (n < end) {
        const float* p = x + (size_t)n * D;
        xb0 = ((const float4*)(p      ))[lane];
        xb1 = ((const float4*)(p + 128))[lane];
        xb2 = ((const float4*)(p + 256))[lane];
        xb3 = ((const float4*)(p + 384))[lane];
    }
    while (n < end) {
        float4 c0 = xb0, c1 = xb1, c2 = xb2, c3 = xb3;
        int nn = n + NW;
        if (nn < end) {
            const float* p = x + (size_t)nn * D;
            xb0 = ((const float4*)(p      ))[lane];
            xb1 = ((const float4*)(p + 128))[lane];
            xb2 = ((const float4*)(p + 256))[lane];
            xb3 = ((const float4*)(p + 384))[lane];
        }
        float s = c0.x * qr[0]  + c0.y * qr[1]  + c0.z * qr[2]  + c0.w * qr[3]
                + c1.x * qr[4]  + c1.y * qr[5]  + c1.z * qr[6]  + c1.w * qr[7]
                + c2.x * qr[8]  + c2.y * qr[9]  + c2.z * qr[10] + c2.w * qr[11]
                + c3.x * qr[12] + c3.y * qr[13] + c3.z * qr[14] + c3.w * qr[15];
        #pragma unroll
        for (int o = 16; o > 0; o >>= 1) s += __shfl_xor_sync(0xffffffffu, s, o);

        if (s > m) {
            float al = __expf(m - s);   // first iteration: exp(-inf) = 0
            d = d * al + 1.0f;
            r[0]  = r[0]  * al + c0.x;  r[1]  = r[1]  * al + c0.y;
            r[2]  = r[2]  * al + c0.z;  r[3]  = r[3]  * al + c0.w;
            r[4]  = r[4]  * al + c1.x;  r[5]  = r[5]  * al + c1.y;
            r[6]  = r[6]  * al + c1.z;  r[7]  = r[7]  * al + c1.w;
            r[8]  = r[8]  * al + c2.x;  r[9]  = r[9]  * al + c2.y;
            r[10] = r[10] * al + c2.z;  r[11] = r[11] * al + c2.w;
            r[12] = r[12] * al + c3.x;  r[13] = r[13] * al + c3.y;
            r[14] = r[14] * al + c3.z;  r[15] = r[15] * al + c3.w;
            m = s;
        } else {
            float wv = __expf(s - m);
            d += wv;
            r[0]  += wv * c0.x;  r[1]  += wv * c0.y;  r[2]  += wv * c0.z;  r[3]  += wv * c0.w;
            r[4]  += wv * c1.x;  r[5]  += wv * c1.y;  r[6]  += wv * c1.z;  r[7]  += wv * c1.w;
            r[8]  += wv * c2.x;  r[9]  += wv * c2.y;  r[10] += wv * c2.z;  r[11] += wv * c2.w;
            r[12] += wv * c3.x;  r[13] += wv * c3.y;  r[14] += wv * c3.z;  r[15] += wv * c3.w;
        }
        n = nn;
    }

    // per-warp partials to shared (canonical column order)
    if (lane == 0) { msh[w] = m; dsh[w] = d; }
    #pragma unroll
    for (int c = 0; c < 4; c++)
        *(float4*)&rsh[w][c * 128 + lane * 4] =
            make_float4(r[c * 4], r[c * 4 + 1], r[c * 4 + 2], r[c * 4 + 3]);
    __syncthreads();

    // block combine: thread t owns cols t and t+256
    float M = msh[0];
    #pragma unroll
    for (int p = 1; p < NW; p++) M = fmaxf(M, msh[p]);
    float Mg = isfinite(M) ? M : 0.0f;
    float dd = 0.0f, r0 = 0.0f, r1 = 0.0f;
    #pragma unroll
    for (int p = 0; p < NW; p++) {
        float sc = __expf(msh[p] - Mg);
        dd += dsh[p] * sc;
        r0 += rsh[p][t] * sc;
        r1 += rsh[p][t + 256] * sc;
    }
    int pid = b * SPLITS + sp;
    g_pr[(size_t)pid * D + t]       = r0;
    g_pr[(size_t)pid * D + t + 256] = r1;
    if (t == 0) { g_pm[pid] = M; g_pd[pid] = dd; }

    // last block for this graph merges all split partials
    __threadfence();
    if (t == 0) {
        int c = atomicAdd(&g_cnt[b], 1);
        is_last = (c == SPLITS - 1);
    }
    __syncthreads();
    if (!is_last) return;

    __shared__ float sm[SPLITS], sd[SPLITS];
    if (t < SPLITS) {
        sm[t] = g_pm[b * SPLITS + t];
        sd[t] = g_pd[b * SPLITS + t];
    }
    __syncthreads();
    float MM = -INFINITY;
    #pragma unroll
    for (int p = 0; p < SPLITS; p++) MM = fmaxf(MM, sm[p]);
    if (!isfinite(MM)) MM = 0.0f;
    float denom = 0.0f;
    float scale[SPLITS];
    #pragma unroll
    for (int p = 0; p < SPLITS; p++) {
        scale[p] = expf(sm[p] - MM);
        denom += sd[p] * scale[p];
    }
    float inv = 1.0f / (denom + 1e-16f);
    float r0f = 0.0f, r1f = 0.0f;
    #pragma unroll
    for (int p = 0; p < SPLITS; p++) {
        const float* pr = g_pr + (size_t)(b * SPLITS + p) * D;
        r0f += pr[t]       * scale[p];
        r1f += pr[t + 256] * scale[p];
    }
    g_qstar[b * QS + D + t]       = r0f * inv;
    g_qstar[b * QS + D + t + 256] = r1f * inv;
    if (t == 0) g_cnt[b] = 0;   // reset for next pass / next replay
}

// ---------------- projection: out[b,o] = qstar[b,:] . W_proj[o,:] + b_proj[o] ----------------
__global__ void k_proj(const float* __restrict__ Wp, const float* __restrict__ bp,
                       float* __restrict__ out) {
    int gw = (blockIdx.x * 256 + threadIdx.x) >> 5;
    int lane = threadIdx.x & 31;
    int bb = gw >> 8, o = gw & 255;
    const float* qr = g_qstar + bb * QS;
    const float* wr = Wp + o * QS;
    float s = 0.0f;
    #pragma unroll
    for (int it = 0; it < QS / 128; it++) {
        int k = lane * 4 + it * 128;
        float4 a = *(const float4*)(qr + k);
        float4 w = *(const float4*)(wr + k);
        s += a.x * w.x + a.y * w.y + a.z * w.z + a.w * w.w;
    }
    #pragma unroll
    for (int off = 16; off > 0; off >>= 1) s += __shfl_xor_sync(0xffffffffu, s, off);
    if (lane == 0) out[gw] = s + bp[o];
}

// ---------------- launch ----------------
extern "C" void kernel_launch(void* const* d_in, const int* in_sizes, int n_in,
                              void* d_out, int out_size) {
    const float* x      = (const float*)d_in[0];
    const void*  batch  = d_in[1];
    const float* W_ih   = (const float*)d_in[2];
    const float* W_hh   = (const float*)d_in[3];
    const float* b_ih   = (const float*)d_in[4];
    const float* b_hh   = (const float*)d_in[5];
    const float* W_proj = (const float*)d_in[6];
    const float* b_proj = (const float*)d_in[7];
    (void)n_in; (void)out_size;
    int N = in_sizes[1];

    int init_blocks = WCOMB_BLKS + STEP0_BLKS + (N + 255) / 256;
    k_init<<<init_blocks, 256>>>(batch, N, W_ih, W_hh, b_ih, b_hh);

    // step 0 attention (h from biases written by k_init)
    k_attn_part<<<B * SPLITS, 256>>>(x);

    // steps 1,2
    for (int s = 1; s < 3; s++) {
        k_gemm_gates<<<dim3(FOURD / BN, B / BM, KSPLIT), 256>>>();
        k_lstm_ew<<<(B * D / 4 + 255) / 256, 256>>>();
        k_attn_part<<<B * SPLITS, 256>>>(x);
    }

    k_proj<<<(B * 256) / 8, 256>>>(W_proj, b_proj, (float*)d_out);
}

// round 8
// speedup vs baseline: 1.1232x; 1.1059x over previous
#include <cuda_runtime.h>
#include <math.h>
#include <stdint.h>

#define D      512
#define B      256
#define FOURD  2048
#define QS     1024   // 2*D
#define SPLITS 8
#define NW     8      // warps per attn block (256 threads)

#define BM 128
#define BN 128
#define BK 16
#define KSPLIT 8
#define KCH (QS / KSPLIT)   // 128
#define NIT (KCH / BK)      // 8

// ---- scratch (no allocations allowed) ----
__device__ float g_WcombT[QS * FOURD];  // [1024][2048] K-major (transposed combined weight)
__device__ float g_bsum[FOURD];
__device__ float g_qstar[B * QS];       // [h | r] row-major (attention/proj consumer)
__device__ float g_qstarT[QS * B];      // [1024][256] K-major (GEMM consumer)
__device__ float g_c[B * D];
__device__ float g_gpart[KSPLIT][B * FOURD];
__device__ int   g_segoff[B + 1];
// split-attention partials
__device__ float g_pm[B * SPLITS];
__device__ float g_pd[B * SPLITS];
__device__ float g_pr[B * SPLITS * D];

__device__ __forceinline__ float sigf(float v) { return 1.0f / (1.0f + expf(-v)); }

__device__ __forceinline__ void cp_async16(uint32_t dst_smem, const void* src) {
    asm volatile("cp.async.cg.shared.global [%0], [%1], 16;" :: "r"(dst_smem), "l"(src));
}

// ---------------- fused init: WcombT transpose + bsum + step0 + segscan ----------------
#define WT_BLKS  ((FOURD / 32) * (QS / 32))   // 64*32 = 2048
#define STEP0_BLKS (B * D / 256)              // 512
__global__ void k_init(const void* __restrict__ raw, int N,
                       const float* __restrict__ W_ih, const float* __restrict__ W_hh,
                       const float* __restrict__ b_ih, const float* __restrict__ b_hh) {
    __shared__ float s[32][33];
    int blk = blockIdx.x;
    int t = threadIdx.x;
    if (blk < WT_BLKS) {
        // WcombT[k][n] = W_ih[n][k] + (k<D ? W_hh[n][k] : 0), via 32x32 shared transpose
        int nt = blk >> 5, kt = blk & 31;
        int tx = t & 31, ty = t >> 5;
        #pragma unroll
        for (int i = 0; i < 4; i++) {
            int n = nt * 32 + ty + i * 8;
            int k = kt * 32 + tx;
            float v = W_ih[(size_t)n * QS + k];
            if (k < D) v += W_hh[(size_t)n * D + k];
            s[ty + i * 8][tx] = v;
        }
        __syncthreads();
        #pragma unroll
        for (int i = 0; i < 4; i++) {
            int k = kt * 32 + ty + i * 8;
            int n = nt * 32 + tx;
            g_WcombT[(size_t)k * FOURD + n] = s[tx][ty + i * 8];
        }
        if (blk < 8) g_bsum[blk * 256 + t] = b_ih[blk * 256 + t] + b_hh[blk * 256 + t];
    } else if (blk < WT_BLKS + STEP0_BLKS) {
        // step 0: h,c from biases only (q_star = 0)
        int idx = (blk - WT_BLKS) * 256 + t;
        int j = idx & (D - 1);
        float gi = b_ih[j]         + b_hh[j];
        float gg = b_ih[2 * D + j] + b_hh[2 * D + j];
        float go = b_ih[3 * D + j] + b_hh[3 * D + j];
        float c  = sigf(gi) * tanhf(gg);
        float h  = sigf(go) * tanhf(c);
        int b = idx >> 9;
        g_c[idx] = c;
        g_qstar[b * QS + j] = h;
        g_qstarT[j * B + b] = h;
    } else {
        // segment-boundary scan; auto-detect int32 vs int64 batch
        const int* p32 = (const int*)raw;
        bool is64 = (p32[N - 1] == 0) || (p32[N - 2] == 0);
        int i = (blk - WT_BLKS - STEP0_BLKS) * 256 + t;
        if (i >= N) return;
        int cur = is64 ? (int)((const long long*)raw)[i] : p32[i];
        if (i == 0) {
            for (int j = 0; j <= cur; j++) g_segoff[j] = 0;
        } else {
            int prev = is64 ? (int)((const long long*)raw)[i - 1] : p32[i - 1];
            for (int j = prev + 1; j <= cur; j++) g_segoff[j] = i;
        }
        if (i == N - 1) {
            for (int j = cur + 1; j <= B; j++) g_segoff[j] = N;
        }
    }
}

// ---------------- LSTM elementwise for steps 1,2 (sums K-split partials + bias) ----------------
__global__ void k_lstm_ew() {
    int idx = blockIdx.x * blockDim.x + threadIdx.x;
    if (idx >= B * D) return;
    int b = idx >> 9, j = idx & (D - 1);
    float gi = g_bsum[j], gf = g_bsum[D + j], gg = g_bsum[2 * D + j], go = g_bsum[3 * D + j];
    #pragma unroll
    for (int z = 0; z < KSPLIT; z++) {
        const float* g = &g_gpart[z][(size_t)b * FOURD];
        gi += g[j]; gf += g[D + j]; gg += g[2 * D + j]; go += g[3 * D + j];
    }
    float c = sigf(gf) * g_c[idx] + sigf(gi) * tanhf(gg);
    float h = sigf(go) * tanhf(c);
    g_c[idx] = c;
    g_qstar[b * QS + j] = h;
    g_qstarT[j * B + b] = h;
}

// ---------------- gates GEMM v3: cp.async 2-stage pipeline, transpose-free K-major loads,
// ----------------  128x128 tile, 8x8 microtile f32x2, split-K=8 ----------------
__global__ void __launch_bounds__(256, 2) k_gemm_gates() {
    __shared__ __align__(16) float As[2][BK][BM];   // 2*16*128*4 = 16KB
    __shared__ __align__(16) float Bs[2][BK][BN];   // 16KB
    int n0 = blockIdx.x * BN, m0 = blockIdx.y * BM, kc = blockIdx.z * KCH;
    int t = threadIdx.x;
    int tx = t & 15, ty = t >> 4;

    unsigned long long acc2[8][4];
    #pragma unroll
    for (int i = 0; i < 8; i++)
        #pragma unroll
        for (int j = 0; j < 4; j++) acc2[i][j] = 0ull;

    // per-thread copy slots: chunks c = t and t+256 of 512 float4-chunks per matrix
    int kr0 = t >> 5,        mq0 = t & 31;          // chunk t
    int kr1 = (t + 256) >> 5, mq1 = t & 31;         // chunk t+256 (mq same since 256 = 8*32)

    const float* srcA = g_qstarT + (size_t)kc * B;
    const float* srcB = g_WcombT + (size_t)kc * FOURD;

    // prologue: stage 0
    {
        cp_async16(__cvta_generic_to_shared(&As[0][kr0][mq0 * 4]), srcA + (size_t)kr0 * B + m0 + mq0 * 4);
        cp_async16(__cvta_generic_to_shared(&As[0][kr1][mq1 * 4]), srcA + (size_t)kr1 * B + m0 + mq1 * 4);
        cp_async16(__cvta_generic_to_shared(&Bs[0][kr0][mq0 * 4]), srcB + (size_t)kr0 * FOURD + n0 + mq0 * 4);
        cp_async16(__cvta_generic_to_shared(&Bs[0][kr1][mq1 * 4]), srcB + (size_t)kr1 * FOURD + n0 + mq1 * 4);
        asm volatile("cp.async.commit_group;");
    }

    int buf = 0;
    for (int it = 0; it < NIT; it++) {
        if (it + 1 < NIT) {
            int kof = (it + 1) * BK;
            int nb = buf ^ 1;
            cp_async16(__cvta_generic_to_shared(&As[nb][kr0][mq0 * 4]), srcA + (size_t)(kof + kr0) * B + m0 + mq0 * 4);
            cp_async16(__cvta_generic_to_shared(&As[nb][kr1][mq1 * 4]), srcA + (size_t)(kof + kr1) * B + m0 + mq1 * 4);
            cp_async16(__cvta_generic_to_shared(&Bs[nb][kr0][mq0 * 4]), srcB + (size_t)(kof + kr0) * FOURD + n0 + mq0 * 4);
            cp_async16(__cvta_generic_to_shared(&Bs[nb][kr1][mq1 * 4]), srcB + (size_t)(kof + kr1) * FOURD + n0 + mq1 * 4);
            asm volatile("cp.async.commit_group;");
            asm volatile("cp.async.wait_group 1;");
        } else {
            asm volatile("cp.async.wait_group 0;");
        }
        __syncthreads();
        #pragma unroll
        for (int kk = 0; kk < BK; kk++) {
            float a[8];
            *(float4*)(a)     = *(const float4*)&As[buf][kk][ty * 8];
            *(float4*)(a + 4) = *(const float4*)&As[buf][kk][ty * 8 + 4];
            unsigned long long b2[4];
            {
                ulonglong2 bl0 = *(const ulonglong2*)&Bs[buf][kk][tx * 8];
                ulonglong2 bl1 = *(const ulonglong2*)&Bs[buf][kk][tx * 8 + 4];
                b2[0] = bl0.x; b2[1] = bl0.y; b2[2] = bl1.x; b2[3] = bl1.y;
            }
            #pragma unroll
            for (int i = 0; i < 8; i++) {
                unsigned long long a2;
                asm("mov.b64 %0, {%1, %1};" : "=l"(a2) : "r"(__float_as_uint(a[i])));
                #pragma unroll
                for (int j = 0; j < 4; j++)
                    asm("fma.rn.f32x2 %0, %1, %2, %0;"
                        : "+l"(acc2[i][j]) : "l"(a2), "l"(b2[j]));
            }
        }
        __syncthreads();
        buf ^= 1;
    }
    #pragma unroll
    for (int i = 0; i < 8; i++) {
        int mrow = m0 + ty * 8 + i;
        unsigned long long* dst =
            (unsigned long long*)&g_gpart[blockIdx.z][(size_t)mrow * FOURD + n0 + tx * 8];
        *(ulonglong2*)(dst)     = make_ulonglong2(acc2[i][0], acc2[i][1]);
        *(ulonglong2*)(dst + 2) = make_ulonglong2(acc2[i][2], acc2[i][3]);
    }
}

// ---------------- split segment attention (round-5 proven shape) ----------------
// lane l owns cols {c*128 + l*4 .. +3}; depth-1 register prefetch, 8 warps/block, SPLITS=8.
__global__ void __launch_bounds__(256) k_attn_part(const float* __restrict__ x) {
    __shared__ __align__(16) float q_sh[D];
    __shared__ __align__(16) float rsh[NW][D];
    __shared__ float msh[NW], dsh[NW];

    int b  = blockIdx.x / SPLITS;
    int sp = blockIdx.x % SPLITS;
    int t = threadIdx.x;
    int w = t >> 5, lane = t & 31;

    int segs = g_segoff[b], sege = g_segoff[b + 1];
    int total = sege - segs;
    int start = segs + (int)(((long long)total * sp) / SPLITS);
    int end   = segs + (int)(((long long)total * (sp + 1)) / SPLITS);

    q_sh[t]       = g_qstar[b * QS + t];
    q_sh[t + 256] = g_qstar[b * QS + t + 256];
    __syncthreads();

    float qr[16];
    #pragma unroll
    for (int c = 0; c < 4; c++) {
        float4 qv = *(const float4*)&q_sh[c * 128 + lane * 4];
        qr[c * 4 + 0] = qv.x; qr[c * 4 + 1] = qv.y;
        qr[c * 4 + 2] = qv.z; qr[c * 4 + 3] = qv.w;
    }

    float m = -INFINITY, d = 0.0f;
    float r[16];
    #pragma unroll
    for (int j = 0; j < 16; j++) r[j] = 0.0f;

    int n = start + w;
    float4 xb0, xb1, xb2, xb3;
    if (n < end) {
        const float* p = x + (size_t)n * D;
        xb0 = ((const float4*)(p      ))[lane];
        xb1 = ((const float4*)(p + 128))[lane];
        xb2 = ((const float4*)(p + 256))[lane];
        xb3 = ((const float4*)(p + 384))[lane];
    }
    while (n < end) {
        float4 c0 = xb0, c1 = xb1, c2 = xb2, c3 = xb3;
        int nn = n + NW;
        if (nn < end) {
            const float* p = x + (size_t)nn * D;
            xb0 = ((const float4*)(p      ))[lane];
            xb1 = ((const float4*)(p + 128))[lane];
            xb2 = ((const float4*)(p + 256))[lane];
            xb3 = ((const float4*)(p + 384))[lane];
        }
        float s = c0.x * qr[0]  + c0.y * qr[1]  + c0.z * qr[2]  + c0.w * qr[3]
                + c1.x * qr[4]  + c1.y * qr[5]  + c1.z * qr[6]  + c1.w * qr[7]
                + c2.x * qr[8]  + c2.y * qr[9]  + c2.z * qr[10] + c2.w * qr[11]
                + c3.x * qr[12] + c3.y * qr[13] + c3.z * qr[14] + c3.w * qr[15];
        #pragma unroll
        for (int o = 16; o > 0; o >>= 1) s += __shfl_xor_sync(0xffffffffu, s, o);

        if (s > m) {
            float al = __expf(m - s);   // first iteration: exp(-inf) = 0
            d = d * al + 1.0f;
            r[0]  = r[0]  * al + c0.x;  r[1]  = r[1]  * al + c0.y;
            r[2]  = r[2]  * al + c0.z;  r[3]  = r[3]  * al + c0.w;
            r[4]  = r[4]  * al + c1.x;  r[5]  = r[5]  * al + c1.y;
            r[6]  = r[6]  * al + c1.z;  r[7]  = r[7]  * al + c1.w;
            r[8]  = r[8]  * al + c2.x;  r[9]  = r[9]  * al + c2.y;
            r[10] = r[10] * al + c2.z;  r[11] = r[11] * al + c2.w;
            r[12] = r[12] * al + c3.x;  r[13] = r[13] * al + c3.y;
            r[14] = r[14] * al + c3.z;  r[15] = r[15] * al + c3.w;
            m = s;
        } else {
            float wv = __expf(s - m);
            d += wv;
            r[0]  += wv * c0.x;  r[1]  += wv * c0.y;  r[2]  += wv * c0.z;  r[3]  += wv * c0.w;
            r[4]  += wv * c1.x;  r[5]  += wv * c1.y;  r[6]  += wv * c1.z;  r[7]  += wv * c1.w;
            r[8]  += wv * c2.x;  r[9]  += wv * c2.y;  r[10] += wv * c2.z;  r[11] += wv * c2.w;
            r[12] += wv * c3.x;  r[13] += wv * c3.y;  r[14] += wv * c3.z;  r[15] += wv * c3.w;
        }
        n = nn;
    }

    // per-warp partials to shared (canonical column order)
    if (lane == 0) { msh[w] = m; dsh[w] = d; }
    #pragma unroll
    for (int c = 0; c < 4; c++)
        *(float4*)&rsh[w][c * 128 + lane * 4] =
            make_float4(r[c * 4], r[c * 4 + 1], r[c * 4 + 2], r[c * 4 + 3]);
    __syncthreads();

    // block combine: thread t owns cols t and t+256
    float M = msh[0];
    #pragma unroll
    for (int p = 1; p < NW; p++) M = fmaxf(M, msh[p]);
    float Mg = isfinite(M) ? M : 0.0f;
    float dd = 0.0f, r0 = 0.0f, r1 = 0.0f;
    #pragma unroll
    for (int p = 0; p < NW; p++) {
        float sc = __expf(msh[p] - Mg);
        dd += dsh[p] * sc;
        r0 += rsh[p][t] * sc;
        r1 += rsh[p][t + 256] * sc;
    }
    int pid = b * SPLITS + sp;
    g_pr[(size_t)pid * D + t]       = r0;
    g_pr[(size_t)pid * D + t + 256] = r1;
    if (t == 0) { g_pm[pid] = M; g_pd[pid] = dd; }
}

// ---------------- combine split partials -> r in g_qstar (+ transposed copy) ----------------
__global__ void k_attn_combine() {
    __shared__ float sm[SPLITS], sd[SPLITS];
    int b = blockIdx.x, t = threadIdx.x;
    if (t < SPLITS) {
        sm[t] = g_pm[b * SPLITS + t];
        sd[t] = g_pd[b * SPLITS + t];
    }
    __syncthreads();
    float M = -INFINITY;
    #pragma unroll
    for (int p = 0; p < SPLITS; p++) M = fmaxf(M, sm[p]);
    if (!isfinite(M)) M = 0.0f;
    float denom = 0.0f;
    float scale[SPLITS];
    #pragma unroll
    for (int p = 0; p < SPLITS; p++) {
        scale[p] = expf(sm[p] - M);
        denom += sd[p] * scale[p];
    }
    float inv = 1.0f / (denom + 1e-16f);
    float r0 = 0.0f, r1 = 0.0f;
    #pragma unroll
    for (int p = 0; p < SPLITS; p++) {
        const float* pr = g_pr + (size_t)(b * SPLITS + p) * D;
        r0 += pr[t]       * scale[p];
        r1 += pr[t + 256] * scale[p];
    }
    r0 *= inv; r1 *= inv;
    g_qstar[b * QS + D + t]        = r0;
    g_qstar[b * QS + D + t + 256]  = r1;
    g_qstarT[(D + t) * B + b]       = r0;
    g_qstarT[(D + t + 256) * B + b] = r1;
}

// ---------------- projection: out[b,o] = qstar[b,:] . W_proj[o,:] + b_proj[o] ----------------
__global__ void k_proj(const float* __restrict__ Wp, const float* __restrict__ bp,
                       float* __restrict__ out) {
    int gw = (blockIdx.x * 256 + threadIdx.x) >> 5;
    int lane = threadIdx.x & 31;
    int bb = gw >> 8, o = gw & 255;
    const float* qr = g_qstar + bb * QS;
    const float* wr = Wp + o * QS;
    float s = 0.0f;
    #pragma unroll
    for (int it = 0; it < QS / 128; it++) {
        int k = lane * 4 + it * 128;
        float4 a = *(const float4*)(qr + k);
        float4 w = *(const float4*)(wr + k);
        s += a.x * w.x + a.y * w.y + a.z * w.z + a.w * w.w;
    }
    #pragma unroll
    for (int off = 16; off > 0; off >>= 1) s += __shfl_xor_sync(0xffffffffu, s, off);
    if (lane == 0) out[gw] = s + bp[o];
}

// ---------------- launch ----------------
extern "C" void kernel_launch(void* const* d_in, const int* in_sizes, int n_in,
                              void* d_out, int out_size) {
    const float* x      = (const float*)d_in[0];
    const void*  batch  = d_in[1];
    const float* W_ih   = (const float*)d_in[2];
    const float* W_hh   = (const float*)d_in[3];
    const float* b_ih   = (const float*)d_in[4];
    const float* b_hh   = (const float*)d_in[5];
    const float* W_proj = (const float*)d_in[6];
    const float* b_proj = (const float*)d_in[7];
    (void)n_in; (void)out_size;
    int N = in_sizes[1];

    int init_blocks = WT_BLKS + STEP0_BLKS + (N + 255) / 256;
    k_init<<<init_blocks, 256>>>(batch, N, W_ih, W_hh, b_ih, b_hh);

    // step 0 attention (h from biases written by k_init)
    k_attn_part<<<B * SPLITS, 256>>>(x);
    k_attn_combine<<<B, 256>>>();

    // steps 1,2
    for (int s = 1; s < 3; s++) {
        k_gemm_gates<<<dim3(FOURD / BN, B / BM, KSPLIT), 256>>>();
        k_lstm_ew<<<(B * D + 255) / 256, 256>>>();
        k_attn_part<<<B * SPLITS, 256>>>(x);
        k_attn_combine<<<B, 256>>>();
    }

    k_proj<<<(B * 256) / 8, 256>>>(W_proj, b_proj, (float*)d_out);
}

// round 9
// speedup vs baseline: 1.1334x; 1.0091x over previous
#include <cuda_runtime.h>
#include <math.h>
#include <stdint.h>

#define D      512
#define B      256
#define FOURD  2048
#define QS     1024   // 2*D
#define SPLITS 8
#define NW     8      // warps per attn block (256 threads)

#define BM 128
#define BN 128
#define BK 16
#define KSPLIT 8
#define KCH (QS / KSPLIT)   // 128
#define NIT (KCH / BK)      // 8

// ---- scratch (no allocations allowed) ----
__device__ float g_WcombT[QS * FOURD];  // [1024][2048] K-major (transposed combined weight)
__device__ float g_bsum[FOURD];
__device__ float g_qstar[B * QS];       // [h | r] row-major (attention/proj consumer)
__device__ float g_qstarT[QS * B];      // [1024][256] K-major (GEMM consumer)
__device__ float g_c[B * D];
__device__ float g_gpart[KSPLIT][B * FOURD];
__device__ int   g_segoff[B + 1];
// split-attention partials
__device__ float g_pm[B * SPLITS];
__device__ float g_pd[B * SPLITS];
__device__ float g_pr[B * SPLITS * D];

__device__ __forceinline__ float sigf(float v) { return 1.0f / (1.0f + expf(-v)); }

__device__ __forceinline__ void cp_async16(uint32_t dst_smem, const void* src) {
    asm volatile("cp.async.cg.shared.global [%0], [%1], 16;" :: "r"(dst_smem), "l"(src));
}

// ---------------- fused init: WcombT transpose + bsum + step0 + segscan ----------------
#define WT_BLKS  ((FOURD / 32) * (QS / 32))   // 64*32 = 2048
#define STEP0_BLKS (B * D / 256)              // 512
__global__ void k_init(const void* __restrict__ raw, int N,
                       const float* __restrict__ W_ih, const float* __restrict__ W_hh,
                       const float* __restrict__ b_ih, const float* __restrict__ b_hh) {
    __shared__ float s[32][33];
    int blk = blockIdx.x;
    int t = threadIdx.x;
    if (blk < WT_BLKS) {
        // WcombT[k][n] = W_ih[n][k] + (k<D ? W_hh[n][k] : 0), via 32x32 shared transpose
        int nt = blk >> 5, kt = blk & 31;
        int tx = t & 31, ty = t >> 5;
        #pragma unroll
        for (int i = 0; i < 4; i++) {
            int n = nt * 32 + ty + i * 8;
            int k = kt * 32 + tx;
            float v = W_ih[(size_t)n * QS + k];
            if (k < D) v += W_hh[(size_t)n * D + k];
            s[ty + i * 8][tx] = v;
        }
        __syncthreads();
        #pragma unroll
        for (int i = 0; i < 4; i++) {
            int k = kt * 32 + ty + i * 8;
            int n = nt * 32 + tx;
            g_WcombT[(size_t)k * FOURD + n] = s[tx][ty + i * 8];
        }
        if (blk < 8) g_bsum[blk * 256 + t] = b_ih[blk * 256 + t] + b_hh[blk * 256 + t];
    } else if (blk < WT_BLKS + STEP0_BLKS) {
        // step 0: h,c from biases only (q_star = 0)
        int idx = (blk - WT_BLKS) * 256 + t;
        int j = idx & (D - 1);
        float gi = b_ih[j]         + b_hh[j];
        float gg = b_ih[2 * D + j] + b_hh[2 * D + j];
        float go = b_ih[3 * D + j] + b_hh[3 * D + j];
        float c  = sigf(gi) * tanhf(gg);
        float h  = sigf(go) * tanhf(c);
        int b = idx >> 9;
        g_c[idx] = c;
        g_qstar[b * QS + j] = h;
        g_qstarT[j * B + b] = h;
    } else {
        // segment-boundary scan; auto-detect int32 vs int64 batch
        const int* p32 = (const int*)raw;
        bool is64 = (p32[N - 1] == 0) || (p32[N - 2] == 0);
        int i = (blk - WT_BLKS - STEP0_BLKS) * 256 + t;
        if (i >= N) return;
        int cur = is64 ? (int)((const long long*)raw)[i] : p32[i];
        if (i == 0) {
            for (int j = 0; j <= cur; j++) g_segoff[j] = 0;
        } else {
            int prev = is64 ? (int)((const long long*)raw)[i - 1] : p32[i - 1];
            for (int j = prev + 1; j <= cur; j++) g_segoff[j] = i;
        }
        if (i == N - 1) {
            for (int j = cur + 1; j <= B; j++) g_segoff[j] = N;
        }
    }
}

// ---------------- LSTM elementwise, float4, 128-thr blocks (sums K-split partials + bias) ----------------
__global__ void __launch_bounds__(128) k_lstm_ew() {
    int idx = blockIdx.x * 128 + threadIdx.x;   // over B*D/4
    if (idx >= B * D / 4) return;
    int b = idx >> 7;
    int j = (idx & 127) * 4;
    float4 gi = *(const float4*)&g_bsum[j];
    float4 gf = *(const float4*)&g_bsum[D + j];
    float4 gg = *(const float4*)&g_bsum[2 * D + j];
    float4 go = *(const float4*)&g_bsum[3 * D + j];
    #pragma unroll
    for (int z = 0; z < KSPLIT; z++) {
        const float* g = &g_gpart[z][(size_t)b * FOURD];
        float4 a = *(const float4*)&g[j];
        float4 f = *(const float4*)&g[D + j];
        float4 c = *(const float4*)&g[2 * D + j];
        float4 o = *(const float4*)&g[3 * D + j];
        gi.x += a.x; gi.y += a.y; gi.z += a.z; gi.w += a.w;
        gf.x += f.x; gf.y += f.y; gf.z += f.z; gf.w += f.w;
        gg.x += c.x; gg.y += c.y; gg.z += c.z; gg.w += c.w;
        go.x += o.x; go.y += o.y; go.z += o.z; go.w += o.w;
    }
    float4 cold = *(const float4*)&g_c[b * D + j];
    float4 cnew, hnew;
    cnew.x = sigf(gf.x) * cold.x + sigf(gi.x) * tanhf(gg.x);
    cnew.y = sigf(gf.y) * cold.y + sigf(gi.y) * tanhf(gg.y);
    cnew.z = sigf(gf.z) * cold.z + sigf(gi.z) * tanhf(gg.z);
    cnew.w = sigf(gf.w) * cold.w + sigf(gi.w) * tanhf(gg.w);
    hnew.x = sigf(go.x) * tanhf(cnew.x);
    hnew.y = sigf(go.y) * tanhf(cnew.y);
    hnew.z = sigf(go.z) * tanhf(cnew.z);
    hnew.w = sigf(go.w) * tanhf(cnew.w);
    *(float4*)&g_c[b * D + j] = cnew;
    *(float4*)&g_qstar[b * QS + j] = hnew;
    g_qstarT[(j + 0) * B + b] = hnew.x;
    g_qstarT[(j + 1) * B + b] = hnew.y;
    g_qstarT[(j + 2) * B + b] = hnew.z;
    g_qstarT[(j + 3) * B + b] = hnew.w;
}

// ---------------- gates GEMM v4: 3-stage cp.async pipeline, ONE barrier per iter,
// ----------------  128x128 tile, 8x8 microtile f32x2, split-K=8 ----------------
__global__ void __launch_bounds__(256, 2) k_gemm_gates() {
    __shared__ __align__(16) float As[3][BK][BM];   // 3*8KB = 24KB
    __shared__ __align__(16) float Bs[3][BK][BN];   // 24KB
    int n0 = blockIdx.x * BN, m0 = blockIdx.y * BM, kc = blockIdx.z * KCH;
    int t = threadIdx.x;
    int tx = t & 15, ty = t >> 4;

    unsigned long long acc2[8][4];
    #pragma unroll
    for (int i = 0; i < 8; i++)
        #pragma unroll
        for (int j = 0; j < 4; j++) acc2[i][j] = 0ull;

    // per-thread copy slots: rows kr0 (0..7) and kr0+8, column group mq
    int kr0 = t >> 5, kr1 = kr0 + 8;
    int mq  = (t & 31) * 4;

    const float* srcA = g_qstarT + (size_t)kc * B;
    const float* srcB = g_WcombT + (size_t)kc * FOURD;

    // prologue: stages 0 and 1
    #pragma unroll
    for (int s = 0; s < 2; s++) {
        int kof = s * BK;
        cp_async16(__cvta_generic_to_shared(&As[s][kr0][mq]), srcA + (size_t)(kof + kr0) * B + m0 + mq);
        cp_async16(__cvta_generic_to_shared(&As[s][kr1][mq]), srcA + (size_t)(kof + kr1) * B + m0 + mq);
        cp_async16(__cvta_generic_to_shared(&Bs[s][kr0][mq]), srcB + (size_t)(kof + kr0) * FOURD + n0 + mq);
        cp_async16(__cvta_generic_to_shared(&Bs[s][kr1][mq]), srcB + (size_t)(kof + kr1) * FOURD + n0 + mq);
        asm volatile("cp.async.commit_group;");
    }

    #pragma unroll
    for (int it = 0; it < NIT; it++) {
        if (it < NIT - 1) asm volatile("cp.async.wait_group 1;");
        else              asm volatile("cp.async.wait_group 0;");
        __syncthreads();   // stage it is resident for everyone; stage (it+2)%3 fully consumed
        if (it + 2 < NIT) {
            int st = (it + 2) % 3;
            int kof = (it + 2) * BK;
            cp_async16(__cvta_generic_to_shared(&As[st][kr0][mq]), srcA + (size_t)(kof + kr0) * B + m0 + mq);
            cp_async16(__cvta_generic_to_shared(&As[st][kr1][mq]), srcA + (size_t)(kof + kr1) * B + m0 + mq);
            cp_async16(__cvta_generic_to_shared(&Bs[st][kr0][mq]), srcB + (size_t)(kof + kr0) * FOURD + n0 + mq);
            cp_async16(__cvta_generic_to_shared(&Bs[st][kr1][mq]), srcB + (size_t)(kof + kr1) * FOURD + n0 + mq);
            asm volatile("cp.async.commit_group;");
        }
        int cb = it % 3;
        #pragma unroll
        for (int kk = 0; kk < BK; kk++) {
            float a[8];
            *(float4*)(a)     = *(const float4*)&As[cb][kk][ty * 8];
            *(float4*)(a + 4) = *(const float4*)&As[cb][kk][ty * 8 + 4];
            unsigned long long b2[4];
            {
                ulonglong2 bl0 = *(const ulonglong2*)&Bs[cb][kk][tx * 8];
                ulonglong2 bl1 = *(const ulonglong2*)&Bs[cb][kk][tx * 8 + 4];
                b2[0] = bl0.x; b2[1] = bl0.y; b2[2] = bl1.x; b2[3] = bl1.y;
            }
            #pragma unroll
            for (int i = 0; i < 8; i++) {
                unsigned long long a2;
                asm("mov.b64 %0, {%1, %1};" : "=l"(a2) : "r"(__float_as_uint(a[i])));
                #pragma unroll
                for (int j = 0; j < 4; j++)
                    asm("fma.rn.f32x2 %0, %1, %2, %0;"
                        : "+l"(acc2[i][j]) : "l"(a2), "l"(b2[j]));
            }
        }
    }
    #pragma unroll
    for (int i = 0; i < 8; i++) {
        int mrow = m0 + ty * 8 + i;
        unsigned long long* dst =
            (unsigned long long*)&g_gpart[blockIdx.z][(size_t)mrow * FOURD + n0 + tx * 8];
        *(ulonglong2*)(dst)     = make_ulonglong2(acc2[i][0], acc2[i][1]);
        *(ulonglong2*)(dst + 2) = make_ulonglong2(acc2[i][2], acc2[i][3]);
    }
}

// ---------------- split segment attention (round-5 proven shape) ----------------
// lane l owns cols {c*128 + l*4 .. +3}; depth-1 register prefetch, 8 warps/block, SPLITS=8.
__global__ void __launch_bounds__(256) k_attn_part(const float* __restrict__ x) {
    __shared__ __align__(16) float q_sh[D];
    __shared__ __align__(16) float rsh[NW][D];
    __shared__ float msh[NW], dsh[NW];

    int b  = blockIdx.x / SPLITS;
    int sp = blockIdx.x % SPLITS;
    int t = threadIdx.x;
    int w = t >> 5, lane = t & 31;

    int segs = g_segoff[b], sege = g_segoff[b + 1];
    int total = sege - segs;
    int start = segs + (int)(((long long)total * sp) / SPLITS);
    int end   = segs + (int)(((long long)total * (sp + 1)) / SPLITS);

    q_sh[t]       = g_qstar[b * QS + t];
    q_sh[t + 256] = g_qstar[b * QS + t + 256];
    __syncthreads();

    float qr[16];
    #pragma unroll
    for (int c = 0; c < 4; c++) {
        float4 qv = *(const float4*)&q_sh[c * 128 + lane * 4];
        qr[c * 4 + 0] = qv.x; qr[c * 4 + 1] = qv.y;
        qr[c * 4 + 2] = qv.z; qr[c * 4 + 3] = qv.w;
    }

    float m = -INFINITY, d = 0.0f;
    float r[16];
    #pragma unroll
    for (int j = 0; j < 16; j++) r[j] = 0.0f;

    int n = start + w;
    float4 xb0, xb1, xb2, xb3;
    if (n < end) {
        const float* p = x + (size_t)n * D;
        xb0 = ((const float4*)(p      ))[lane];
        xb1 = ((const float4*)(p + 128))[lane];
        xb2 = ((const float4*)(p + 256))[lane];
        xb3 = ((const float4*)(p + 384))[lane];
    }
    while (n < end) {
        float4 c0 = xb0, c1 = xb1, c2 = xb2, c3 = xb3;
        int nn = n + NW;
        if (nn < end) {
            const float* p = x + (size_t)nn * D;
            xb0 = ((const float4*)(p      ))[lane];
            xb1 = ((const float4*)(p + 128))[lane];
            xb2 = ((const float4*)(p + 256))[lane];
            xb3 = ((const float4*)(p + 384))[lane];
        }
        float s = c0.x * qr[0]  + c0.y * qr[1]  + c0.z * qr[2]  + c0.w * qr[3]
                + c1.x * qr[4]  + c1.y * qr[5]  + c1.z * qr[6]  + c1.w * qr[7]
                + c2.x * qr[8]  + c2.y * qr[9]  + c2.z * qr[10] + c2.w * qr[11]
                + c3.x * qr[12] + c3.y * qr[13] + c3.z * qr[14] + c3.w * qr[15];
        #pragma unroll
        for (int o = 16; o > 0; o >>= 1) s += __shfl_xor_sync(0xffffffffu, s, o);

        if (s > m) {
            float al = __expf(m - s);   // first iteration: exp(-inf) = 0
            d = d * al + 1.0f;
            r[0]  = r[0]  * al + c0.x;  r[1]  = r[1]  * al + c0.y;
            r[2]  = r[2]  * al + c0.z;  r[3]  = r[3]  * al + c0.w;
            r[4]  = r[4]  * al + c1.x;  r[5]  = r[5]  * al + c1.y;
            r[6]  = r[6]  * al + c1.z;  r[7]  = r[7]  * al + c1.w;
            r[8]  = r[8]  * al + c2.x;  r[9]  = r[9]  * al + c2.y;
            r[10] = r[10] * al + c2.z;  r[11] = r[11] * al + c2.w;
            r[12] = r[12] * al + c3.x;  r[13] = r[13] * al + c3.y;
            r[14] = r[14] * al + c3.z;  r[15] = r[15] * al + c3.w;
            m = s;
        } else {
            float wv = __expf(s - m);
            d += wv;
            r[0]  += wv * c0.x;  r[1]  += wv * c0.y;  r[2]  += wv * c0.z;  r[3]  += wv * c0.w;
            r[4]  += wv * c1.x;  r[5]  += wv * c1.y;  r[6]  += wv * c1.z;  r[7]  += wv * c1.w;
            r[8]  += wv * c2.x;  r[9]  += wv * c2.y;  r[10] += wv * c2.z;  r[11] += wv * c2.w;
            r[12] += wv * c3.x;  r[13] += wv * c3.y;  r[14] += wv * c3.z;  r[15] += wv * c3.w;
        }
        n = nn;
    }

    // per-warp partials to shared (canonical column order)
    if (lane == 0) { msh[w] = m; dsh[w] = d; }
    #pragma unroll
    for (int c = 0; c < 4; c++)
        *(float4*)&rsh[w][c * 128 + lane * 4] =
            make_float4(r[c * 4], r[c * 4 + 1], r[c * 4 + 2], r[c * 4 + 3]);
    __syncthreads();

    // block combine: thread t owns cols t and t+256
    float M = msh[0];
    #pragma unroll
    for (int p = 1; p < NW; p++) M = fmaxf(M, msh[p]);
    float Mg = isfinite(M) ? M : 0.0f;
    float dd = 0.0f, r0 = 0.0f, r1 = 0.0f;
    #pragma unroll
    for (int p = 0; p < NW; p++) {
        float sc = __expf(msh[p] - Mg);
        dd += dsh[p] * sc;
        r0 += rsh[p][t] * sc;
        r1 += rsh[p][t + 256] * sc;
    }
    int pid = b * SPLITS + sp;
    g_pr[(size_t)pid * D + t]       = r0;
    g_pr[(size_t)pid * D + t + 256] = r1;
    if (t == 0) { g_pm[pid] = M; g_pd[pid] = dd; }
}

// ---------------- combine split partials -> r in g_qstar (+ transposed copy) ----------------
__global__ void k_attn_combine() {
    __shared__ float sm[SPLITS], sd[SPLITS];
    int b = blockIdx.x, t = threadIdx.x;
    if (t < SPLITS) {
        sm[t] = g_pm[b * SPLITS + t];
        sd[t] = g_pd[b * SPLITS + t];
    }
    __syncthreads();
    float M = -INFINITY;
    #pragma unroll
    for (int p = 0; p < SPLITS; p++) M = fmaxf(M, sm[p]);
    if (!isfinite(M)) M = 0.0f;
    float denom = 0.0f;
    float scale[SPLITS];
    #pragma unroll
    for (int p = 0; p < SPLITS; p++) {
        scale[p] = expf(sm[p] - M);
        denom += sd[p] * scale[p];
    }
    float inv = 1.0f / (denom + 1e-16f);
    float r0 = 0.0f, r1 = 0.0f;
    #pragma unroll
    for (int p = 0; p < SPLITS; p++) {
        const float* pr = g_pr + (size_t)(b * SPLITS + p) * D;
        r0 += pr[t]       * scale[p];
        r1 += pr[t + 256] * scale[p];
    }
    r0 *= inv; r1 *= inv;
    g_qstar[b * QS + D + t]        = r0;
    g_qstar[b * QS + D + t + 256]  = r1;
    g_qstarT[(D + t) * B + b]       = r0;
    g_qstarT[(D + t + 256) * B + b] = r1;
}

// ---------------- projection: out[b,o] = qstar[b,:] . W_proj[o,:] + b_proj[o] ----------------
__global__ void k_proj(const float* __restrict__ Wp, const float* __restrict__ bp,
                       float* __restrict__ out) {
    int gw = (blockIdx.x * 256 + threadIdx.x) >> 5;
    int lane = threadIdx.x & 31;
    int bb = gw >> 8, o = gw & 255;
    const float* qr = g_qstar + bb * QS;
    const float* wr = Wp + o * QS;
    float s = 0.0f;
    #pragma unroll
    for (int it = 0; it < QS / 128; it++) {
        int k = lane * 4 + it * 128;
        float4 a = *(const float4*)(qr + k);
        float4 w = *(const float4*)(wr + k);
        s += a.x * w.x + a.y * w.y + a.z * w.z + a.w * w.w;
    }
    #pragma unroll
    for (int off = 16; off > 0; off >>= 1) s += __shfl_xor_sync(0xffffffffu, s, off);
    if (lane == 0) out[gw] = s + bp[o];
}

// ---------------- launch ----------------
extern "C" void kernel_launch(void* const* d_in, const int* in_sizes, int n_in,
                              void* d_out, int out_size) {
    const float* x      = (const float*)d_in[0];
    const void*  batch  = d_in[1];
    const float* W_ih   = (const float*)d_in[2];
    const float* W_hh   = (const float*)d_in[3];
    const float* b_ih   = (const float*)d_in[4];
    const float* b_hh   = (const float*)d_in[5];
    const float* W_proj = (const float*)d_in[6];
    const float* b_proj = (const float*)d_in[7];
    (void)n_in; (void)out_size;
    int N = in_sizes[1];

    int init_blocks = WT_BLKS + STEP0_BLKS + (N + 255) / 256;
    k_init<<<init_blocks, 256>>>(batch, N, W_ih, W_hh, b_ih, b_hh);

    // step 0 attention (h from biases written by k_init)
    k_attn_part<<<B * SPLITS, 256>>>(x);
    k_attn_combine<<<B, 256>>>();

    // steps 1,2
    for (int s = 1; s < 3; s++) {
        k_gemm_gates<<<dim3(FOURD / BN, B / BM, KSPLIT), 256>>>();
        k_lstm_ew<<<(B * D / 4 + 127) / 128, 128>>>();
        k_attn_part<<<B * SPLITS, 256>>>(x);
        k_attn_combine<<<B, 256>>>();
    }

    k_proj<<<(B * 256) / 8, 256>>>(W_proj, b_proj, (float*)d_out);
}